// round 5
// baseline (speedup 1.0000x reference)
#include <cuda_runtime.h>
#include <math.h>

#define BB 64
#define DD 256
#define NN 16
#define RR 16

__device__ __forceinline__ float warp_sum(float v) {
#pragma unroll
    for (int off = 16; off; off >>= 1)
        v += __shfl_xor_sync(0xffffffffu, v, off);
    return v;
}

// Four independent butterfly reductions, interleaved for ILP (hides SHFL lat)
__device__ __forceinline__ void red4(float& a0, float& a1, float& a2, float& a3) {
#pragma unroll
    for (int off = 16; off; off >>= 1) {
        a0 += __shfl_xor_sync(0xffffffffu, a0, off);
        a1 += __shfl_xor_sync(0xffffffffu, a1, off);
        a2 += __shfl_xor_sync(0xffffffffu, a2, off);
        a3 += __shfl_xor_sync(0xffffffffu, a3, off);
    }
}

__device__ __forceinline__ float dot8(float4 a, float4 b, float4 wa, float4 wb) {
    return a.x * wa.x + a.y * wa.y + a.z * wa.z + a.w * wa.w +
           b.x * wb.x + b.y * wb.y + b.z * wb.z + b.w * wb.w;
}

// ---------------------------------------------------------------------------
// Fully fused: one block per batch, 512 threads (16 warps).
// rmsnorm -> in-proj (768 warp-dots, shared-resident) -> conv+silu (4 slots)
// -> xproj -> dt+softplus -> closed-form scan -> gate -> out-proj -> rmsnorm.
// ---------------------------------------------------------------------------
__global__ __launch_bounds__(512, 1) void k_fused(
    const float* __restrict__ x1g, const float* __restrict__ x2g,
    const float* __restrict__ norm_w,
    const float* __restrict__ conv_w, const float* __restrict__ conv_b,
    const float* __restrict__ in_w,
    const float* __restrict__ xproj_w,
    const float* __restrict__ dt_w, const float* __restrict__ dt_b,
    const float* __restrict__ out_w,
    const float* __restrict__ A_log, const float* __restrict__ Dvec,
    const int* __restrict__ lp,
    float* __restrict__ out)
{
    const int b    = blockIdx.x;
    const int t    = threadIdx.x;
    const int ch   = t & 255;
    const int half = t >> 8;
    const int lane = t & 31;
    const int warp = t >> 5;     // 0..15

    __shared__ __align__(16) float s_xn1[DD];   // rmsnorm(x1)*norm_w
    __shared__ __align__(16) float s_xn2[DD];   // rmsnorm(x2)*norm_w
    __shared__ __align__(16) float s_x1c[DD];
    __shared__ __align__(16) float s_res1[DD];
    __shared__ __align__(16) float s_x2c[DD];
    __shared__ __align__(16) float s_x2s[4][DD];
    __shared__ float s_B[4][NN];
    __shared__ float s_Cs[NN];
    __shared__ float s_draw[4][NN];
    __shared__ __align__(16) float s_yp[2 * DD];
    __shared__ __align__(16) float s_y[DD];
    __shared__ __align__(16) float s_out[DD];
    __shared__ float s_red[16];

    // --- phase 0: rmsnorm of x1 (lower half) and x2 (upper half) ---
    const float nw = norm_w[ch];
    const float xv = (half == 0 ? x1g : x2g)[b * DD + ch];
    {
        float ss = warp_sum(xv * xv);
        if (lane == 0) s_red[warp] = ss;
    }
    __syncthreads();
    {
        float tot = 0.0f;
#pragma unroll
        for (int w = 0; w < 8; w++) tot += s_red[half * 8 + w];
        float scale = rsqrtf(tot * (1.0f / DD) + 1e-5f);
        (half == 0 ? s_xn1 : s_xn2)[ch] = xv * scale * nw;
    }
    __syncthreads();

    // --- phase 1: in-projection, 768 dots = 48 per warp, ILP x4 ---
#pragma unroll
    for (int g = 0; g < 12; g++) {
        float acc[4];
#pragma unroll
        for (int i = 0; i < 4; i++) {
            const int j = warp * 48 + g * 4 + i;        // 0..767
            const float* src = (j < 512) ? s_xn1 : s_xn2;
            const int wrow   = (j < 512) ? j : (j - 512);
            const float4* wr = (const float4*)(in_w + wrow * DD);
            const float4* xr = (const float4*)src;
            acc[i] = dot8(xr[lane], xr[lane + 32], wr[lane], wr[lane + 32]);
        }
        red4(acc[0], acc[1], acc[2], acc[3]);
        if (lane < 4) {
            const int j = warp * 48 + g * 4 + lane;
            float v = (lane == 0) ? acc[0] : (lane == 1) ? acc[1]
                    : (lane == 2) ? acc[2] : acc[3];
            if (j < 256)       s_x1c[j]        = v;
            else if (j < 512)  s_res1[j - 256] = v;
            else               s_x2c[j - 512]  = v;
        }
    }
    __syncthreads();

    // --- phase 2: conv + silu (4 distinct timeslots: suffix sums of k=4) ---
    const float4 cw = ((const float4*)conv_w)[ch];
    const float  cb = conv_b[ch];
    const float S0 = cw.w;
    const float S1 = cw.z + S0;
    const float S2 = cw.y + S1;
    const float S3 = cw.x + S2;
    const float x1cv = s_x1c[ch];
    const float x2cv = s_x2c[ch];
    float x1r[4];
    {
        float v;
        v = x1cv * S0 + cb; x1r[0] = v / (1.0f + __expf(-v));
        v = x1cv * S1 + cb; x1r[1] = v / (1.0f + __expf(-v));
        v = x1cv * S2 + cb; x1r[2] = v / (1.0f + __expf(-v));
        v = x1cv * S3 + cb; x1r[3] = v / (1.0f + __expf(-v));
        if (half == 0) {
            v = x2cv * S0 + cb; s_x2s[0][ch] = v / (1.0f + __expf(-v));
            v = x2cv * S1 + cb; s_x2s[1][ch] = v / (1.0f + __expf(-v));
            v = x2cv * S2 + cb; s_x2s[2][ch] = v / (1.0f + __expf(-v));
            v = x2cv * S3 + cb; s_x2s[3][ch] = v / (1.0f + __expf(-v));
        }
    }
    __syncthreads();

    // Prefetch per-channel constants; latency hidden under the xproj dots.
    float dw[16];
    {
        const float4* p = (const float4*)(dt_w + ch * RR);
        ((float4*)dw)[0] = p[0]; ((float4*)dw)[1] = p[1];
        ((float4*)dw)[2] = p[2]; ((float4*)dw)[3] = p[3];
    }
    float alr[8];
    {
        const float4* p = (const float4*)(A_log + ch * NN + half * 8);
        ((float4*)alr)[0] = p[0]; ((float4*)alr)[1] = p[1];
    }
    const float dtb = dt_b[ch];
    const float Dv  = Dvec[ch];

    // --- phase 3: xdbl = x2s @ xproj_w.T : 192 dots = 12 per warp, x4 ILP ---
#pragma unroll
    for (int g = 0; g < 3; g++) {
        float acc[4];
#pragma unroll
        for (int i = 0; i < 4; i++) {
            const int j = warp * 12 + g * 4 + i;
            const int ts = j / 48, c = j % 48;
            const float4* wr = (const float4*)(xproj_w + c * DD);
            const float4* xr = (const float4*)(s_x2s[ts]);
            acc[i] = dot8(xr[lane], xr[lane + 32], wr[lane], wr[lane + 32]);
        }
        red4(acc[0], acc[1], acc[2], acc[3]);
        if (lane < 4) {
            const int j = warp * 12 + g * 4 + lane;
            const int ts = j / 48, c = j % 48;
            float v = (lane == 0) ? acc[0] : (lane == 1) ? acc[1]
                    : (lane == 2) ? acc[2] : acc[3];
            if (c < 16)       s_draw[ts][c]   = v;
            else if (c < 32)  s_B[ts][c - 16] = v;
            else if (ts == 3) s_Cs[c - 32]    = v;
        }
    }
    __syncthreads();

    // --- phase 4: delta = softplus(draw @ dt_w.T + dt_b), u = delta * x1s ---
    float dts[4], u[4];
#pragma unroll
    for (int ts = 0; ts < 4; ts++) {
        float acc = dtb;
#pragma unroll
        for (int r = 0; r < 16; r++) acc += s_draw[ts][r] * dw[r];
        dts[ts] = (acc > 20.0f) ? acc : log1pf(__expf(acc));
        u[ts]   = dts[ts] * x1r[ts];
    }

    // --- phase 5: closed-form scan, each half owns 8 of 16 state dims ---
    const int l = lp ? *lp : 256;
    const float m = (float)(l - 3);
    float y = 0.0f;
#pragma unroll
    for (int n = 0; n < 8; n++) {
        const int ng = half * 8 + n;
        float a  = -__expf(alr[n]);
        float e1 = __expf(dts[1] * a);
        float e2 = __expf(dts[2] * a);
        float e3 = __expf(dts[3] * a);
        float h = u[0] * s_B[0][ng];
        h = e1 * h + u[1] * s_B[1][ng];
        h = e2 * h + u[2] * s_B[2][ng];
        float p3 = __expf(m * dts[3] * a);
        float gg = 1.0f - e3;
        float geo = (gg > 1e-30f) ? (1.0f - p3) / gg : m;
        h = p3 * h + u[3] * s_B[3][ng] * geo;
        y += h * s_Cs[ng];
    }
    s_yp[t] = y;
    __syncthreads();

    if (half == 0) {
        float yy = s_yp[ch] + s_yp[ch + 256] + x1r[3] * Dv;
        float res = s_res1[ch];
        yy *= res / (1.0f + __expf(-res));   // * silu(res1)
        s_y[ch] = yy;
    }
    __syncthreads();

    // --- phase 6: out projection: 256 dots = 16 per warp, x4 ILP ---
    {
        const float4* yp4 = (const float4*)s_y;
        const float4 ya = yp4[lane], yb = yp4[lane + 32];
#pragma unroll
        for (int g = 0; g < 4; g++) {
            float acc[4];
#pragma unroll
            for (int i = 0; i < 4; i++) {
                const int c = warp * 16 + g * 4 + i;
                const float4* wr = (const float4*)(out_w + c * DD);
                acc[i] = dot8(ya, yb, wr[lane], wr[lane + 32]);
            }
            red4(acc[0], acc[1], acc[2], acc[3]);
            if (lane < 4) {
                const int c = warp * 16 + g * 4 + lane;
                s_out[c] = (lane == 0) ? acc[0] : (lane == 1) ? acc[1]
                         : (lane == 2) ? acc[2] : acc[3];
            }
        }
    }
    __syncthreads();

    // --- phase 7: final rmsnorm over d, write output row ---
    if (half == 0) {
        float v = s_out[ch];
        float ss = warp_sum(v * v);
        if (lane == 0) s_red[warp] = ss;
    }
    __syncthreads();
    if (half == 0) {
        float tot = 0.0f;
#pragma unroll
        for (int w = 0; w < 8; w++) tot += s_red[w];
        float scale = rsqrtf(tot * (1.0f / DD) + 1e-5f);
        out[b * DD + ch] = s_out[ch] * scale * nw;
    }
}

// ---------------------------------------------------------------------------
extern "C" void kernel_launch(void* const* d_in, const int* in_sizes, int n_in,
                              void* d_out, int out_size) {
    (void)in_sizes; (void)out_size;
    const float* x1      = (const float*)d_in[0];
    const float* x2      = (const float*)d_in[1];
    const float* norm_w  = (const float*)d_in[2];
    const float* conv_w  = (const float*)d_in[3];
    const float* conv_b  = (const float*)d_in[4];
    const float* in_w    = (const float*)d_in[5];
    const float* xproj_w = (const float*)d_in[6];
    const float* dt_w    = (const float*)d_in[7];
    const float* dt_b    = (const float*)d_in[8];
    const float* out_w   = (const float*)d_in[9];
    const float* A_log   = (const float*)d_in[10];
    const float* Dv      = (const float*)d_in[11];
    const int*   lp      = (n_in > 12) ? (const int*)d_in[12] : nullptr;
    float* out = (float*)d_out;

    k_fused<<<BB, 512>>>(x1, x2, norm_w, conv_w, conv_b, in_w, xproj_w,
                         dt_w, dt_b, out_w, A_log, Dv, lp, out);
}